// round 13
// baseline (speedup 1.0000x reference)
#include <cuda_runtime.h>
#include <cuda_bf16.h>
#include <math.h>
#include <stdint.h>

#define NB 2
#define NW 16
#define NN 1000
#define NT 16000       // NW*NN
#define FIN 16
#define ESP 16000      // spatial edges
#define DE 8
#define HID 128
#define NLAYER 3

// ---------------- scratch (device globals; no cudaMalloc allowed) ----------------
__device__ float g_x[NB * NT * HID];          // 16.4 MB
__device__ float g_qkv[NB * NT * 3 * HID];    // 49 MB   layout (row, 384): Q|K|V
__device__ float g_msg[NB * NT * HID];        // 16.4 MB
__device__ float g_y[NB * NT * HID];          // 16.4 MB
__device__ float g_film[(ESP + 1) * 2 * HID]; // 16.4 MB
__device__ float g_meanea[DE];
__device__ int   g_hist[NN];
__device__ int   g_indptr[NN + 1];
__device__ int   g_cursor[NN];
__device__ int   g_spedge[ESP];
// pre-split weights: 12 matrices (l*4 + {q,k,v,o}); [N=128][K=128] bf16 row-major,
// hi part in g_wA, lo part in g_wB
__device__ __nv_bfloat16 g_wA[12 * 128 * 128];
__device__ __nv_bfloat16 g_wB[12 * 128 * 128];

// ---------------- bf16 2-split helper ----------------
__device__ __forceinline__ void split2(float v, unsigned short& h, unsigned short& l) {
    __nv_bfloat16 b1 = __float2bfloat16_rn(v);
    float r = v - __bfloat162float(b1);
    __nv_bfloat16 b2 = __float2bfloat16_rn(r);
    h = __bfloat16_as_ushort(b1);
    l = __bfloat16_as_ushort(b2);
}

// ---------------- CSR build over the 1000 spatial dst nodes ----------------
__global__ void k_zero() {
    int t = blockIdx.x * blockDim.x + threadIdx.x;
    if (t < NN) g_hist[t] = 0;
}

__global__ void k_hist(const int* __restrict__ ei) {
    int j = blockIdx.x * blockDim.x + threadIdx.x;
    if (j < ESP) atomicAdd(&g_hist[ei[ESP + j]], 1);
}

__global__ void k_scan() {   // 1 block, 1024 threads
    __shared__ int sh[1024];
    int t = threadIdx.x;
    int v = (t < NN) ? g_hist[t] : 0;
    sh[t] = v;
    __syncthreads();
    for (int off = 1; off < 1024; off <<= 1) {
        int u = (t >= off) ? sh[t - off] : 0;
        __syncthreads();
        sh[t] += u;
        __syncthreads();
    }
    if (t < NN) { g_indptr[t + 1] = sh[t]; g_cursor[t] = sh[t] - v; }
    if (t == 0) g_indptr[0] = 0;
}

__global__ void k_fill(const int* __restrict__ ei) {
    int j = blockIdx.x * blockDim.x + threadIdx.x;
    if (j < ESP) {
        int d = ei[ESP + j];
        int p = atomicAdd(&g_cursor[d], 1);
        g_spedge[p] = j;
    }
}

// ---------------- mean of spatial edge attrs ----------------
__global__ void k_meanea(const float* __restrict__ ea) {
    __shared__ float sh[256];
    int t = threadIdx.x, c = blockIdx.x;
    float s = 0.f;
    for (int r = t; r < ESP; r += 256) s += ea[r * DE + c];
    sh[t] = s;
    __syncthreads();
    for (int off = 128; off; off >>= 1) {
        if (t < off) sh[t] += sh[t + off];
        __syncthreads();
    }
    if (t == 0) g_meanea[c] = sh[0] / (float)ESP;
}

// ---------------- weight pre-split: 12 blocks, one matrix each ----------------
__global__ void __launch_bounds__(256) k_wsplit(const float* __restrict__ qw,
                                                const float* __restrict__ kw,
                                                const float* __restrict__ vw,
                                                const float* __restrict__ ow) {
    int blk = blockIdx.x;        // l*4 + s
    int l = blk >> 2, s = blk & 3;
    const float* W = (s == 0) ? qw : (s == 1) ? kw : (s == 2) ? vw : ow;
    W += (size_t)l * HID * HID;
    __nv_bfloat16* dA = g_wA + (size_t)blk * 128 * 128;
    __nv_bfloat16* dB = g_wB + (size_t)blk * 128 * 128;
    for (int idx = threadIdx.x; idx < 128 * 128; idx += 256) {
        int n = idx >> 7, k = idx & 127;
        float w = W[k * 128 + n];
        unsigned short h, lo;
        split2(w, h, lo);
        dA[n * 128 + k] = __ushort_as_bfloat16(h);
        dB[n * 128 + k] = __ushort_as_bfloat16(lo);
    }
}

// ---------------- input projection (B*NT, 16) @ (16,128) ----------------
__global__ void __launch_bounds__(128) k_inproj(const float* __restrict__ xw,
                                                const float* __restrict__ w,
                                                const float* __restrict__ b) {
    __shared__ float a[8][FIN];
    int t = threadIdx.x;
    int r0 = blockIdx.x * 8;
    a[t / 16][t % 16] = xw[(size_t)(r0 + t / 16) * FIN + (t % 16)];
    __syncthreads();
    float wk[FIN];
#pragma unroll
    for (int k = 0; k < FIN; k++) wk[k] = w[k * HID + t];
    float bb = b[t];
#pragma unroll
    for (int rr = 0; rr < 8; rr++) {
        float s = bb;
#pragma unroll
        for (int k = 0; k < FIN; k++) s += a[rr][k] * wk[k];
        g_x[(size_t)(r0 + rr) * HID + t] = s;
    }
}

// ---------------- FiLM: (16001, 8) @ (8, 256) ----------------
__global__ void __launch_bounds__(256) k_film(const float* __restrict__ ea,
                                              const float* __restrict__ fw,
                                              const float* __restrict__ fb) {
    __shared__ float at[DE];
    int j = blockIdx.x, c = threadIdx.x;
    if (c < DE) at[c] = (j < ESP) ? ea[j * DE + c] : g_meanea[c];
    __syncthreads();
    float s = fb[c];
#pragma unroll
    for (int k = 0; k < DE; k++) s += at[k] * fw[k * 256 + c];
    g_film[(size_t)j * 256 + c] = s;
}

// ================= mma.sync bf16-split-2 GEMM =================
#define KP 136
#define TILE_B (128 * KP * 2)
#define OFF_A1 0
#define OFF_A2 (TILE_B)
#define OFF_B1 (2 * TILE_B)
#define OFF_B2 (3 * TILE_B)
#define OFF_BIAS (4 * TILE_B)
#define SMEM_MMA (OFF_BIAS + 512)

#define MMA16816(D, A0, A1_, A2_, A3_, B0, B1_)                                  \
    asm volatile(                                                                \
        "mma.sync.aligned.m16n8k16.row.col.f32.bf16.bf16.f32 "                   \
        "{%0,%1,%2,%3}, {%4,%5,%6,%7}, {%8,%9}, {%0,%1,%2,%3};"                  \
        : "+f"(D[0]), "+f"(D[1]), "+f"(D[2]), "+f"(D[3])                         \
        : "r"(A0), "r"(A1_), "r"(A2_), "r"(A3_), "r"(B0), "r"(B1_))

__global__ void __launch_bounds__(256, 1)
k_gemm_mma(int mode, int matBase,
           const float* __restrict__ bq, const float* __restrict__ bk,
           const float* __restrict__ bv, int ldc) {
    extern __shared__ char smem[];
    __nv_bfloat16* sA1 = (__nv_bfloat16*)(smem + OFF_A1);
    __nv_bfloat16* sA2 = (__nv_bfloat16*)(smem + OFF_A2);
    __nv_bfloat16* sB1 = (__nv_bfloat16*)(smem + OFF_B1);
    __nv_bfloat16* sB2 = (__nv_bfloat16*)(smem + OFF_B2);
    float* sbias = (float*)(smem + OFF_BIAS);

    int tid = threadIdx.x;
    int z = blockIdx.y;
    int r0 = blockIdx.x * 128;
    int mat = matBase + z;
    int cOff = z * HID;
    const float* __restrict__ A = (mode == 0) ? g_x : g_msg;
    float* __restrict__ C = (mode == 0) ? g_qkv : g_y;
    const float* __restrict__ bias = (z == 0) ? bq : (z == 1) ? bk : bv;

    if (tid < 128) sbias[tid] = bias[tid];

    for (int idx = tid; idx < 4096; idx += 256) {
        int row = idx >> 5, k4 = (idx & 31) << 2;
        float4 a = *(const float4*)(A + (size_t)(r0 + row) * 128 + k4);
        unsigned short h0, l0, h1, l1, h2, l2, h3, l3;
        split2(a.x, h0, l0); split2(a.y, h1, l1);
        split2(a.z, h2, l2); split2(a.w, h3, l3);
        uint2 hv = make_uint2((uint32_t)h0 | ((uint32_t)h1 << 16),
                              (uint32_t)h2 | ((uint32_t)h3 << 16));
        uint2 lv = make_uint2((uint32_t)l0 | ((uint32_t)l1 << 16),
                              (uint32_t)l2 | ((uint32_t)l3 << 16));
        *(uint2*)(sA1 + row * KP + k4) = hv;
        *(uint2*)(sA2 + row * KP + k4) = lv;
    }
    {
        const uint4* srcA = (const uint4*)(g_wA + (size_t)mat * 128 * 128);
        const uint4* srcB = (const uint4*)(g_wB + (size_t)mat * 128 * 128);
        for (int i = tid; i < 2048; i += 256) {
            int row = i >> 4, q = i & 15;
            ((uint4*)(sB1 + row * KP))[q] = srcA[i];
            ((uint4*)(sB2 + row * KP))[q] = srcB[i];
        }
    }
    __syncthreads();

    int wid = tid >> 5, lane = tid & 31;
    int warpM = wid & 3, warpN = wid >> 2;
    int g = lane >> 2, tg = lane & 3;
    int mrow0 = warpM * 32;
    int ncol0 = warpN * 64;

    float acc[2][8][4];
#pragma unroll
    for (int m = 0; m < 2; m++)
#pragma unroll
        for (int nf = 0; nf < 8; nf++)
#pragma unroll
            for (int j = 0; j < 4; j++) acc[m][nf][j] = 0.f;

#pragma unroll
    for (int pass = 0; pass < 3; pass++) {
        const __nv_bfloat16* As = (pass < 2) ? sA1 : sA2;
        const __nv_bfloat16* Bs = (pass == 1) ? sB2 : sB1;
#pragma unroll
        for (int k0 = 0; k0 < 128; k0 += 16) {
            uint32_t afr[2][4];
#pragma unroll
            for (int m = 0; m < 2; m++) {
                const __nv_bfloat16* ab = As + (mrow0 + m * 16 + g) * KP + k0 + tg * 2;
                afr[m][0] = *(const uint32_t*)(ab);
                afr[m][1] = *(const uint32_t*)(ab + 8 * KP);
                afr[m][2] = *(const uint32_t*)(ab + 8);
                afr[m][3] = *(const uint32_t*)(ab + 8 * KP + 8);
            }
#pragma unroll
            for (int nf = 0; nf < 8; nf++) {
                const __nv_bfloat16* bb = Bs + (ncol0 + nf * 8 + g) * KP + k0 + tg * 2;
                uint32_t b0r = *(const uint32_t*)(bb);
                uint32_t b1r = *(const uint32_t*)(bb + 8);
                MMA16816(acc[0][nf], afr[0][0], afr[0][1], afr[0][2], afr[0][3], b0r, b1r);
                MMA16816(acc[1][nf], afr[1][0], afr[1][1], afr[1][2], afr[1][3], b0r, b1r);
            }
        }
    }

#pragma unroll
    for (int m = 0; m < 2; m++) {
        int r = r0 + mrow0 + m * 16 + g;
#pragma unroll
        for (int nf = 0; nf < 8; nf++) {
            int c = ncol0 + nf * 8 + tg * 2;
            float2 v0 = make_float2(acc[m][nf][0] + sbias[c], acc[m][nf][1] + sbias[c + 1]);
            float2 v1 = make_float2(acc[m][nf][2] + sbias[c], acc[m][nf][3] + sbias[c + 1]);
            *(float2*)(C + (size_t)r * ldc + cOff + c) = v0;
            *(float2*)(C + (size_t)(r + 8) * ldc + cOff + c) = v1;
        }
    }
}

// ================ graph attention v2: CTA per spatial dst node =================
// 256 threads = 8 warps; warp handles 4 of the 32 (b,w) combos.
// Spatial edges in chunks of 8: film rows (gamma|beta, 1KB each) staged in smem
// ONCE per chunk and reused by all 32 combos (32x film-traffic reduction).
// Online softmax state per combo lives in registers across chunks.
#define ACHUNK 8
__global__ void __launch_bounds__(256) k_attn2(const int* __restrict__ ei) {
    __shared__ float s_film[ACHUNK][256];
    __shared__ int   s_src[ACHUNK];
    __shared__ float s_mean[256];

    int d = blockIdx.x;
    int tid = threadIdx.x;
    int wid = tid >> 5, lane = tid & 31;

    s_mean[tid] = g_film[(size_t)ESP * 256 + tid];

    int beg = g_indptr[d], nsp = g_indptr[d + 1] - beg;

    // per-combo state (combo = wid*4 + c; b = combo>>4, w = combo&15)
    float4 q[4];
    float m[4], ssum[4];
    float4 acc[4];
#pragma unroll
    for (int c = 0; c < 4; c++) {
        int cmb = wid * 4 + c;
        int b = cmb >> 4, w = cmb & 15;
        const float* qrow = g_qkv + ((size_t)(b * NT + w * NN + d)) * 384;
        q[c] = *(const float4*)(qrow + lane * 4);
        m[c] = -INFINITY; ssum[c] = 0.f;
        acc[c] = make_float4(0.f, 0.f, 0.f, 0.f);
    }

    for (int c0 = 0; c0 < nsp; c0 += ACHUNK) {
        int nc = min(ACHUNK, nsp - c0);
        __syncthreads();                     // protect smem reuse from previous chunk
        for (int idx = tid; idx < nc * 256; idx += 256) {
            int e = idx >> 8, t = idx & 255;
            int j = g_spedge[beg + c0 + e];
            s_film[e][t] = g_film[(size_t)j * 256 + t];
            if (t == 0) s_src[e] = ei[j];
        }
        __syncthreads();
        for (int e = 0; e < nc; e++) {
            int s = s_src[e];
            float4 ga = *(const float4*)(&s_film[e][lane * 4]);
            float4 be = *(const float4*)(&s_film[e][128 + lane * 4]);
#pragma unroll
            for (int c = 0; c < 4; c++) {
                int cmb = wid * 4 + c;
                int b = cmb >> 4, w = cmb & 15;
                const float* krow = g_qkv + ((size_t)(b * NT + w * NN + s)) * 384 + 128;
                float4 k = *(const float4*)(krow + lane * 4);
                float4 v = *(const float4*)(krow + 128 + lane * 4);
                float p = q[c].x * (k.x * (1.f + ga.x) + be.x)
                        + q[c].y * (k.y * (1.f + ga.y) + be.y)
                        + q[c].z * (k.z * (1.f + ga.z) + be.z)
                        + q[c].w * (k.w * (1.f + ga.w) + be.w);
                p += __shfl_xor_sync(0xffffffffu, p, 4);
                p += __shfl_xor_sync(0xffffffffu, p, 2);
                p += __shfl_xor_sync(0xffffffffu, p, 1);
                float logit = p * 0.1767766952966369f;   // 1/sqrt(32)
                float mn = fmaxf(m[c], logit);
                float sc = __expf(m[c] - mn);
                float wt = __expf(logit - mn);
                ssum[c] = ssum[c] * sc + wt;
                acc[c].x = acc[c].x * sc + wt * v.x;
                acc[c].y = acc[c].y * sc + wt * v.y;
                acc[c].z = acc[c].z * sc + wt * v.z;
                acc[c].w = acc[c].w * sc + wt * v.w;
                m[c] = mn;
            }
        }
    }

    // temporal edge (w>0): src = same node at window w-1, film = mean
    {
        float4 ga = *(const float4*)(&s_mean[lane * 4]);
        float4 be = *(const float4*)(&s_mean[128 + lane * 4]);
#pragma unroll
        for (int c = 0; c < 4; c++) {
            int cmb = wid * 4 + c;
            int b = cmb >> 4, w = cmb & 15;
            if (w == 0) continue;
            const float* krow = g_qkv + ((size_t)(b * NT + (w - 1) * NN + d)) * 384 + 128;
            float4 k = *(const float4*)(krow + lane * 4);
            float4 v = *(const float4*)(krow + 128 + lane * 4);
            float p = q[c].x * (k.x * (1.f + ga.x) + be.x)
                    + q[c].y * (k.y * (1.f + ga.y) + be.y)
                    + q[c].z * (k.z * (1.f + ga.z) + be.z)
                    + q[c].w * (k.w * (1.f + ga.w) + be.w);
            p += __shfl_xor_sync(0xffffffffu, p, 4);
            p += __shfl_xor_sync(0xffffffffu, p, 2);
            p += __shfl_xor_sync(0xffffffffu, p, 1);
            float logit = p * 0.1767766952966369f;
            float mn = fmaxf(m[c], logit);
            float sc = __expf(m[c] - mn);
            float wt = __expf(logit - mn);
            ssum[c] = ssum[c] * sc + wt;
            acc[c].x = acc[c].x * sc + wt * v.x;
            acc[c].y = acc[c].y * sc + wt * v.y;
            acc[c].z = acc[c].z * sc + wt * v.z;
            acc[c].w = acc[c].w * sc + wt * v.w;
            m[c] = mn;
        }
    }

#pragma unroll
    for (int c = 0; c < 4; c++) {
        int cmb = wid * 4 + c;
        int b = cmb >> 4, w = cmb & 15;
        float inv = 1.f / (ssum[c] + 1e-16f);
        float4 o = make_float4(acc[c].x * inv, acc[c].y * inv,
                               acc[c].z * inv, acc[c].w * inv);
        *(float4*)(g_msg + ((size_t)(b * NT + w * NN + d)) * HID + lane * 4) = o;
    }
}

// ---------------- residual + layernorm, in-place on g_x (2 rows per block) ----------------
__global__ void __launch_bounds__(256) k_ln(const float* __restrict__ gamma,
                                            const float* __restrict__ beta) {
    int row = blockIdx.x * 2 + (threadIdx.x >> 7);
    int t = threadIdx.x & 127;
    size_t idx = (size_t)row * HID + t;
    float v = g_x[idx] + g_y[idx];
    float a = v, q = v * v;
#pragma unroll
    for (int off = 16; off; off >>= 1) {
        a += __shfl_xor_sync(0xffffffffu, a, off);
        q += __shfl_xor_sync(0xffffffffu, q, off);
    }
    __shared__ float s1[8], s2[8];
    int wid = threadIdx.x >> 5;
    if ((threadIdx.x & 31) == 0) { s1[wid] = a; s2[wid] = q; }
    __syncthreads();
    int base = (threadIdx.x >> 7) << 2;    // 0 or 4
    float ta = s1[base] + s1[base + 1] + s1[base + 2] + s1[base + 3];
    float tq = s2[base] + s2[base + 1] + s2[base + 2] + s2[base + 3];
    float mu = ta * (1.f / HID);
    float var = tq * (1.f / HID) - mu * mu;
    g_x[idx] = (v - mu) * rsqrtf(var + 1e-5f) * gamma[t] + beta[t];
}

// ---------------- head ----------------
__global__ void __launch_bounds__(256) k_head(const float* __restrict__ hw,
                                              const float* __restrict__ hb,
                                              float* __restrict__ out) {
    int gwarp = (blockIdx.x * blockDim.x + threadIdx.x) >> 5;
    if (gwarp >= NB * NN) return;
    int lane = threadIdx.x & 31;
    int b = gwarp / NN, n = gwarp - b * NN;
    const float* xr = g_x + ((size_t)(b * NT + (NW - 1) * NN + n)) * HID;
    float4 xv = *(const float4*)(xr + lane * 4);
    float4 wv = *(const float4*)(hw + lane * 4);
    float p = xv.x * wv.x + xv.y * wv.y + xv.z * wv.z + xv.w * wv.w;
#pragma unroll
    for (int off = 16; off; off >>= 1) p += __shfl_xor_sync(0xffffffffu, p, off);
    if (lane == 0) {
        float z = p + hb[0];
        out[gwarp] = fmaxf(z, 0.f) + log1pf(__expf(-fabsf(z)));
    }
}

// ---------------- launch ----------------
extern "C" void kernel_launch(void* const* d_in, const int* in_sizes, int n_in,
                              void* d_out, int out_size) {
    const float* xw  = (const float*)d_in[0];
    const int*   ei  = (const int*)d_in[1];
    const float* ea  = (const float*)d_in[2];
    const float* inw = (const float*)d_in[3];
    const float* inb = (const float*)d_in[4];
    const float* qw  = (const float*)d_in[5];
    const float* qb  = (const float*)d_in[6];
    const float* kw  = (const float*)d_in[7];
    const float* kb  = (const float*)d_in[8];
    const float* vw  = (const float*)d_in[9];
    const float* vb  = (const float*)d_in[10];
    const float* fw  = (const float*)d_in[11];
    const float* fb  = (const float*)d_in[12];
    const float* ow  = (const float*)d_in[13];
    const float* ob  = (const float*)d_in[14];
    const float* lng = (const float*)d_in[15];
    const float* lnb = (const float*)d_in[16];
    const float* hw  = (const float*)d_in[17];
    const float* hb  = (const float*)d_in[18];
    float* out = (float*)d_out;

    cudaFuncSetAttribute(k_gemm_mma, cudaFuncAttributeMaxDynamicSharedMemorySize,
                         SMEM_MMA);

    // CSR over spatial dst + mean edge attr + weight pre-split
    k_zero<<<(NN + 255) / 256, 256>>>();
    k_hist<<<(ESP + 255) / 256, 256>>>(ei);
    k_scan<<<1, 1024>>>();
    k_fill<<<(ESP + 255) / 256, 256>>>(ei);
    k_meanea<<<DE, 256>>>(ea);
    k_wsplit<<<12, 256>>>(qw, kw, vw, ow);

    // input projection
    k_inproj<<<(NB * NT) / 8, 128>>>(xw, inw, inb);

    const int M = NB * NT;  // 32000
    dim3 gQKV(M / 128, 3);
    dim3 gO(M / 128, 1);

    for (int l = 0; l < NLAYER; l++) {
        k_film<<<ESP + 1, 256>>>(ea, fw + (size_t)l * DE * 256, fb + (size_t)l * 256);
        k_gemm_mma<<<gQKV, 256, SMEM_MMA>>>(0, l * 4,
                                            qb + l * HID, kb + l * HID, vb + l * HID,
                                            384);
        k_attn2<<<NN, 256>>>(ei);
        k_gemm_mma<<<gO, 256, SMEM_MMA>>>(1, l * 4 + 3,
                                          ob + l * HID, ob, ob, 128);
        k_ln<<<M / 2, 256>>>(lng + l * HID, lnb + l * HID);
    }

    k_head<<<(NB * NN + 7) / 8, 256>>>(hw, hb, out);
}

// round 16
// speedup vs baseline: 1.0514x; 1.0514x over previous
#include <cuda_runtime.h>
#include <cuda_bf16.h>
#include <math.h>
#include <stdint.h>

#define NB 2
#define NW 16
#define NN 1000
#define NT 16000       // NW*NN
#define FIN 16
#define ESP 16000      // spatial edges
#define DE 8
#define HID 128
#define NLAYER 3

// ---------------- scratch (device globals; no cudaMalloc allowed) ----------------
__device__ float g_x[NB * NT * HID];          // 16.4 MB
__device__ float g_qkv[NB * NT * 3 * HID];    // 49 MB   layout (row, 384): Q|K|V
__device__ float g_msg[NB * NT * HID];        // 16.4 MB
__device__ float g_y[NB * NT * HID];          // 16.4 MB
__device__ float g_film[(ESP + 1) * 2 * HID]; // 16.4 MB
__device__ float g_meanea[DE];
__device__ int   g_hist[NN];
__device__ int   g_indptr[NN + 1];
__device__ int   g_cursor[NN];
__device__ int   g_spedge[ESP];
// pre-split weights: 12 matrices (l*4 + {q,k,v,o}); [N=128][K=128] bf16 row-major,
// hi part in g_wA, lo part in g_wB
__device__ __nv_bfloat16 g_wA[12 * 128 * 128];
__device__ __nv_bfloat16 g_wB[12 * 128 * 128];

// ---------------- bf16 2-split helper ----------------
__device__ __forceinline__ void split2(float v, unsigned short& h, unsigned short& l) {
    __nv_bfloat16 b1 = __float2bfloat16_rn(v);
    float r = v - __bfloat162float(b1);
    __nv_bfloat16 b2 = __float2bfloat16_rn(r);
    h = __bfloat16_as_ushort(b1);
    l = __bfloat16_as_ushort(b2);
}

// ---------------- CSR build over the 1000 spatial dst nodes ----------------
__global__ void k_zero() {
    int t = blockIdx.x * blockDim.x + threadIdx.x;
    if (t < NN) g_hist[t] = 0;
}

__global__ void k_hist(const int* __restrict__ ei) {
    int j = blockIdx.x * blockDim.x + threadIdx.x;
    if (j < ESP) atomicAdd(&g_hist[ei[ESP + j]], 1);
}

__global__ void k_scan() {   // 1 block, 1024 threads
    __shared__ int sh[1024];
    int t = threadIdx.x;
    int v = (t < NN) ? g_hist[t] : 0;
    sh[t] = v;
    __syncthreads();
    for (int off = 1; off < 1024; off <<= 1) {
        int u = (t >= off) ? sh[t - off] : 0;
        __syncthreads();
        sh[t] += u;
        __syncthreads();
    }
    if (t < NN) { g_indptr[t + 1] = sh[t]; g_cursor[t] = sh[t] - v; }
    if (t == 0) g_indptr[0] = 0;
}

__global__ void k_fill(const int* __restrict__ ei) {
    int j = blockIdx.x * blockDim.x + threadIdx.x;
    if (j < ESP) {
        int d = ei[ESP + j];
        int p = atomicAdd(&g_cursor[d], 1);
        g_spedge[p] = j;
    }
}

// ---------------- mean of spatial edge attrs ----------------
__global__ void k_meanea(const float* __restrict__ ea) {
    __shared__ float sh[256];
    int t = threadIdx.x, c = blockIdx.x;
    float s = 0.f;
    for (int r = t; r < ESP; r += 256) s += ea[r * DE + c];
    sh[t] = s;
    __syncthreads();
    for (int off = 128; off; off >>= 1) {
        if (t < off) sh[t] += sh[t + off];
        __syncthreads();
    }
    if (t == 0) g_meanea[c] = sh[0] / (float)ESP;
}

// ---------------- weight pre-split: 12 blocks, one matrix each ----------------
__global__ void __launch_bounds__(256) k_wsplit(const float* __restrict__ qw,
                                                const float* __restrict__ kw,
                                                const float* __restrict__ vw,
                                                const float* __restrict__ ow) {
    int blk = blockIdx.x;        // l*4 + s
    int l = blk >> 2, s = blk & 3;
    const float* W = (s == 0) ? qw : (s == 1) ? kw : (s == 2) ? vw : ow;
    W += (size_t)l * HID * HID;
    __nv_bfloat16* dA = g_wA + (size_t)blk * 128 * 128;
    __nv_bfloat16* dB = g_wB + (size_t)blk * 128 * 128;
    for (int idx = threadIdx.x; idx < 128 * 128; idx += 256) {
        int n = idx >> 7, k = idx & 127;
        float w = W[k * 128 + n];
        unsigned short h, lo;
        split2(w, h, lo);
        dA[n * 128 + k] = __ushort_as_bfloat16(h);
        dB[n * 128 + k] = __ushort_as_bfloat16(lo);
    }
}

// ---------------- input projection (B*NT, 16) @ (16,128) ----------------
__global__ void __launch_bounds__(128) k_inproj(const float* __restrict__ xw,
                                                const float* __restrict__ w,
                                                const float* __restrict__ b) {
    __shared__ float a[8][FIN];
    int t = threadIdx.x;
    int r0 = blockIdx.x * 8;
    a[t / 16][t % 16] = xw[(size_t)(r0 + t / 16) * FIN + (t % 16)];
    __syncthreads();
    float wk[FIN];
#pragma unroll
    for (int k = 0; k < FIN; k++) wk[k] = w[k * HID + t];
    float bb = b[t];
#pragma unroll
    for (int rr = 0; rr < 8; rr++) {
        float s = bb;
#pragma unroll
        for (int k = 0; k < FIN; k++) s += a[rr][k] * wk[k];
        g_x[(size_t)(r0 + rr) * HID + t] = s;
    }
}

// ---------------- FiLM: (16001, 8) @ (8, 256) ----------------
__global__ void __launch_bounds__(256) k_film(const float* __restrict__ ea,
                                              const float* __restrict__ fw,
                                              const float* __restrict__ fb) {
    __shared__ float at[DE];
    int j = blockIdx.x, c = threadIdx.x;
    if (c < DE) at[c] = (j < ESP) ? ea[j * DE + c] : g_meanea[c];
    __syncthreads();
    float s = fb[c];
#pragma unroll
    for (int k = 0; k < DE; k++) s += at[k] * fw[k * 256 + c];
    g_film[(size_t)j * 256 + c] = s;
}

// ================= mma.sync bf16-split-2 GEMM =================
#define KP 136
#define TILE_B (128 * KP * 2)
#define OFF_A1 0
#define OFF_A2 (TILE_B)
#define OFF_B1 (2 * TILE_B)
#define OFF_B2 (3 * TILE_B)
#define OFF_BIAS (4 * TILE_B)
#define SMEM_MMA (OFF_BIAS + 512)

#define MMA16816(D, A0, A1_, A2_, A3_, B0, B1_)                                  \
    asm volatile(                                                                \
        "mma.sync.aligned.m16n8k16.row.col.f32.bf16.bf16.f32 "                   \
        "{%0,%1,%2,%3}, {%4,%5,%6,%7}, {%8,%9}, {%0,%1,%2,%3};"                  \
        : "+f"(D[0]), "+f"(D[1]), "+f"(D[2]), "+f"(D[3])                         \
        : "r"(A0), "r"(A1_), "r"(A2_), "r"(A3_), "r"(B0), "r"(B1_))

__global__ void __launch_bounds__(256, 1)
k_gemm_mma(int mode, int matBase,
           const float* __restrict__ bq, const float* __restrict__ bk,
           const float* __restrict__ bv, int ldc) {
    extern __shared__ char smem[];
    __nv_bfloat16* sA1 = (__nv_bfloat16*)(smem + OFF_A1);
    __nv_bfloat16* sA2 = (__nv_bfloat16*)(smem + OFF_A2);
    __nv_bfloat16* sB1 = (__nv_bfloat16*)(smem + OFF_B1);
    __nv_bfloat16* sB2 = (__nv_bfloat16*)(smem + OFF_B2);
    float* sbias = (float*)(smem + OFF_BIAS);

    int tid = threadIdx.x;
    int z = blockIdx.y;
    int r0 = blockIdx.x * 128;
    int mat = matBase + z;
    int cOff = z * HID;
    const float* __restrict__ A = (mode == 0) ? g_x : g_msg;
    float* __restrict__ C = (mode == 0) ? g_qkv : g_y;
    const float* __restrict__ bias = (z == 0) ? bq : (z == 1) ? bk : bv;

    if (tid < 128) sbias[tid] = bias[tid];

    for (int idx = tid; idx < 4096; idx += 256) {
        int row = idx >> 5, k4 = (idx & 31) << 2;
        float4 a = *(const float4*)(A + (size_t)(r0 + row) * 128 + k4);
        unsigned short h0, l0, h1, l1, h2, l2, h3, l3;
        split2(a.x, h0, l0); split2(a.y, h1, l1);
        split2(a.z, h2, l2); split2(a.w, h3, l3);
        uint2 hv = make_uint2((uint32_t)h0 | ((uint32_t)h1 << 16),
                              (uint32_t)h2 | ((uint32_t)h3 << 16));
        uint2 lv = make_uint2((uint32_t)l0 | ((uint32_t)l1 << 16),
                              (uint32_t)l2 | ((uint32_t)l3 << 16));
        *(uint2*)(sA1 + row * KP + k4) = hv;
        *(uint2*)(sA2 + row * KP + k4) = lv;
    }
    {
        const uint4* srcA = (const uint4*)(g_wA + (size_t)mat * 128 * 128);
        const uint4* srcB = (const uint4*)(g_wB + (size_t)mat * 128 * 128);
        for (int i = tid; i < 2048; i += 256) {
            int row = i >> 4, q = i & 15;
            ((uint4*)(sB1 + row * KP))[q] = srcA[i];
            ((uint4*)(sB2 + row * KP))[q] = srcB[i];
        }
    }
    __syncthreads();

    int wid = tid >> 5, lane = tid & 31;
    int warpM = wid & 3, warpN = wid >> 2;
    int g = lane >> 2, tg = lane & 3;
    int mrow0 = warpM * 32;
    int ncol0 = warpN * 64;

    float acc[2][8][4];
#pragma unroll
    for (int m = 0; m < 2; m++)
#pragma unroll
        for (int nf = 0; nf < 8; nf++)
#pragma unroll
            for (int j = 0; j < 4; j++) acc[m][nf][j] = 0.f;

#pragma unroll
    for (int pass = 0; pass < 3; pass++) {
        const __nv_bfloat16* As = (pass < 2) ? sA1 : sA2;
        const __nv_bfloat16* Bs = (pass == 1) ? sB2 : sB1;
#pragma unroll
        for (int k0 = 0; k0 < 128; k0 += 16) {
            uint32_t afr[2][4];
#pragma unroll
            for (int m = 0; m < 2; m++) {
                const __nv_bfloat16* ab = As + (mrow0 + m * 16 + g) * KP + k0 + tg * 2;
                afr[m][0] = *(const uint32_t*)(ab);
                afr[m][1] = *(const uint32_t*)(ab + 8 * KP);
                afr[m][2] = *(const uint32_t*)(ab + 8);
                afr[m][3] = *(const uint32_t*)(ab + 8 * KP + 8);
            }
#pragma unroll
            for (int nf = 0; nf < 8; nf++) {
                const __nv_bfloat16* bb = Bs + (ncol0 + nf * 8 + g) * KP + k0 + tg * 2;
                uint32_t b0r = *(const uint32_t*)(bb);
                uint32_t b1r = *(const uint32_t*)(bb + 8);
                MMA16816(acc[0][nf], afr[0][0], afr[0][1], afr[0][2], afr[0][3], b0r, b1r);
                MMA16816(acc[1][nf], afr[1][0], afr[1][1], afr[1][2], afr[1][3], b0r, b1r);
            }
        }
    }

#pragma unroll
    for (int m = 0; m < 2; m++) {
        int r = r0 + mrow0 + m * 16 + g;
#pragma unroll
        for (int nf = 0; nf < 8; nf++) {
            int c = ncol0 + nf * 8 + tg * 2;
            float2 v0 = make_float2(acc[m][nf][0] + sbias[c], acc[m][nf][1] + sbias[c + 1]);
            float2 v1 = make_float2(acc[m][nf][2] + sbias[c], acc[m][nf][3] + sbias[c + 1]);
            *(float2*)(C + (size_t)r * ldc + cOff + c) = v0;
            *(float2*)(C + (size_t)(r + 8) * ldc + cOff + c) = v1;
        }
    }
}

// ================ graph attention v3: CTA per dst node, warp per combo =================
// 1024 threads = 32 warps; warp wid owns combo (b = wid>>4, w = wid&15).
// Each warp runs the full online-softmax chain for its combo (same parallelism
// as the 608us v1: 32000 independent warps), while film rows are staged in smem
// once per 8-edge chunk and shared by all 32 warps (32x film-traffic reduction).
#define ACHUNK 8
__global__ void __launch_bounds__(1024) k_attn3(const int* __restrict__ ei) {
    __shared__ float s_film[ACHUNK][256];
    __shared__ int   s_src[ACHUNK];
    __shared__ float s_mean[256];

    int d = blockIdx.x;
    int tid = threadIdx.x;
    int wid = tid >> 5, lane = tid & 31;
    int b = wid >> 4, w = wid & 15;

    if (tid < 256) s_mean[tid] = g_film[(size_t)ESP * 256 + tid];

    int beg = g_indptr[d], nsp = g_indptr[d + 1] - beg;

    const float* qrow = g_qkv + ((size_t)(b * NT + w * NN + d)) * 384;
    float4 q = *(const float4*)(qrow + lane * 4);
    float m = -INFINITY, ssum = 0.f;
    float4 acc = make_float4(0.f, 0.f, 0.f, 0.f);

    for (int c0 = 0; c0 < nsp; c0 += ACHUNK) {
        int nc = min(ACHUNK, nsp - c0);
        __syncthreads();                       // protect smem reuse from previous chunk
        for (int idx = tid; idx < nc * 256; idx += 1024) {
            int e = idx >> 8, t = idx & 255;
            int j = g_spedge[beg + c0 + e];
            s_film[e][t] = g_film[(size_t)j * 256 + t];
            if (t == 0) s_src[e] = ei[j];
        }
        __syncthreads();
        for (int e = 0; e < nc; e++) {
            int s = s_src[e];
            const float* krow = g_qkv + ((size_t)(b * NT + w * NN + s)) * 384 + 128;
            float4 k = *(const float4*)(krow + lane * 4);
            float4 v = *(const float4*)(krow + 128 + lane * 4);
            float4 ga = *(const float4*)(&s_film[e][lane * 4]);
            float4 be = *(const float4*)(&s_film[e][128 + lane * 4]);
            float p = q.x * (k.x * (1.f + ga.x) + be.x)
                    + q.y * (k.y * (1.f + ga.y) + be.y)
                    + q.z * (k.z * (1.f + ga.z) + be.z)
                    + q.w * (k.w * (1.f + ga.w) + be.w);
            p += __shfl_xor_sync(0xffffffffu, p, 4);
            p += __shfl_xor_sync(0xffffffffu, p, 2);
            p += __shfl_xor_sync(0xffffffffu, p, 1);
            float logit = p * 0.1767766952966369f;   // 1/sqrt(32)
            float mn = fmaxf(m, logit);
            float sc = __expf(m - mn);
            float wt = __expf(logit - mn);
            ssum = ssum * sc + wt;
            acc.x = acc.x * sc + wt * v.x;
            acc.y = acc.y * sc + wt * v.y;
            acc.z = acc.z * sc + wt * v.z;
            acc.w = acc.w * sc + wt * v.w;
            m = mn;
        }
    }

    // temporal edge (w>0): src = same node at window w-1, film = mean
    if (w > 0) {
        const float* krow = g_qkv + ((size_t)(b * NT + (w - 1) * NN + d)) * 384 + 128;
        float4 k = *(const float4*)(krow + lane * 4);
        float4 v = *(const float4*)(krow + 128 + lane * 4);
        float4 ga = *(const float4*)(&s_mean[lane * 4]);
        float4 be = *(const float4*)(&s_mean[128 + lane * 4]);
        float p = q.x * (k.x * (1.f + ga.x) + be.x)
                + q.y * (k.y * (1.f + ga.y) + be.y)
                + q.z * (k.z * (1.f + ga.z) + be.z)
                + q.w * (k.w * (1.f + ga.w) + be.w);
        p += __shfl_xor_sync(0xffffffffu, p, 4);
        p += __shfl_xor_sync(0xffffffffu, p, 2);
        p += __shfl_xor_sync(0xffffffffu, p, 1);
        float logit = p * 0.1767766952966369f;
        float mn = fmaxf(m, logit);
        float sc = __expf(m - mn);
        float wt = __expf(logit - mn);
        ssum = ssum * sc + wt;
        acc.x = acc.x * sc + wt * v.x;
        acc.y = acc.y * sc + wt * v.y;
        acc.z = acc.z * sc + wt * v.z;
        acc.w = acc.w * sc + wt * v.w;
        m = mn;
    }

    float inv = 1.f / (ssum + 1e-16f);
    float4 o = make_float4(acc.x * inv, acc.y * inv, acc.z * inv, acc.w * inv);
    *(float4*)(g_msg + ((size_t)(b * NT + w * NN + d)) * HID + lane * 4) = o;
}

// ---------------- residual + layernorm, in-place on g_x (2 rows per block) ----------------
__global__ void __launch_bounds__(256) k_ln(const float* __restrict__ gamma,
                                            const float* __restrict__ beta) {
    int row = blockIdx.x * 2 + (threadIdx.x >> 7);
    int t = threadIdx.x & 127;
    size_t idx = (size_t)row * HID + t;
    float v = g_x[idx] + g_y[idx];
    float a = v, q = v * v;
#pragma unroll
    for (int off = 16; off; off >>= 1) {
        a += __shfl_xor_sync(0xffffffffu, a, off);
        q += __shfl_xor_sync(0xffffffffu, q, off);
    }
    __shared__ float s1[8], s2[8];
    int wid = threadIdx.x >> 5;
    if ((threadIdx.x & 31) == 0) { s1[wid] = a; s2[wid] = q; }
    __syncthreads();
    int base = (threadIdx.x >> 7) << 2;    // 0 or 4
    float ta = s1[base] + s1[base + 1] + s1[base + 2] + s1[base + 3];
    float tq = s2[base] + s2[base + 1] + s2[base + 2] + s2[base + 3];
    float mu = ta * (1.f / HID);
    float var = tq * (1.f / HID) - mu * mu;
    g_x[idx] = (v - mu) * rsqrtf(var + 1e-5f) * gamma[t] + beta[t];
}

// ---------------- head ----------------
__global__ void __launch_bounds__(256) k_head(const float* __restrict__ hw,
                                              const float* __restrict__ hb,
                                              float* __restrict__ out) {
    int gwarp = (blockIdx.x * blockDim.x + threadIdx.x) >> 5;
    if (gwarp >= NB * NN) return;
    int lane = threadIdx.x & 31;
    int b = gwarp / NN, n = gwarp - b * NN;
    const float* xr = g_x + ((size_t)(b * NT + (NW - 1) * NN + n)) * HID;
    float4 xv = *(const float4*)(xr + lane * 4);
    float4 wv = *(const float4*)(hw + lane * 4);
    float p = xv.x * wv.x + xv.y * wv.y + xv.z * wv.z + xv.w * wv.w;
#pragma unroll
    for (int off = 16; off; off >>= 1) p += __shfl_xor_sync(0xffffffffu, p, off);
    if (lane == 0) {
        float z = p + hb[0];
        out[gwarp] = fmaxf(z, 0.f) + log1pf(__expf(-fabsf(z)));
    }
}

// ---------------- launch ----------------
extern "C" void kernel_launch(void* const* d_in, const int* in_sizes, int n_in,
                              void* d_out, int out_size) {
    const float* xw  = (const float*)d_in[0];
    const int*   ei  = (const int*)d_in[1];
    const float* ea  = (const float*)d_in[2];
    const float* inw = (const float*)d_in[3];
    const float* inb = (const float*)d_in[4];
    const float* qw  = (const float*)d_in[5];
    const float* qb  = (const float*)d_in[6];
    const float* kw  = (const float*)d_in[7];
    const float* kb  = (const float*)d_in[8];
    const float* vw  = (const float*)d_in[9];
    const float* vb  = (const float*)d_in[10];
    const float* fw  = (const float*)d_in[11];
    const float* fb  = (const float*)d_in[12];
    const float* ow  = (const float*)d_in[13];
    const float* ob  = (const float*)d_in[14];
    const float* lng = (const float*)d_in[15];
    const float* lnb = (const float*)d_in[16];
    const float* hw  = (const float*)d_in[17];
    const float* hb  = (const float*)d_in[18];
    float* out = (float*)d_out;

    cudaFuncSetAttribute(k_gemm_mma, cudaFuncAttributeMaxDynamicSharedMemorySize,
                         SMEM_MMA);

    // CSR over spatial dst + mean edge attr + weight pre-split
    k_zero<<<(NN + 255) / 256, 256>>>();
    k_hist<<<(ESP + 255) / 256, 256>>>(ei);
    k_scan<<<1, 1024>>>();
    k_fill<<<(ESP + 255) / 256, 256>>>(ei);
    k_meanea<<<DE, 256>>>(ea);
    k_wsplit<<<12, 256>>>(qw, kw, vw, ow);

    // input projection
    k_inproj<<<(NB * NT) / 8, 128>>>(xw, inw, inb);

    const int M = NB * NT;  // 32000
    dim3 gQKV(M / 128, 3);
    dim3 gO(M / 128, 1);

    for (int l = 0; l < NLAYER; l++) {
        k_film<<<ESP + 1, 256>>>(ea, fw + (size_t)l * DE * 256, fb + (size_t)l * 256);
        k_gemm_mma<<<gQKV, 256, SMEM_MMA>>>(0, l * 4,
                                            qb + l * HID, kb + l * HID, vb + l * HID,
                                            384);
        k_attn3<<<NN, 1024>>>(ei);
        k_gemm_mma<<<gO, 256, SMEM_MMA>>>(1, l * 4 + 3,
                                          ob + l * HID, ob, ob, 128);
        k_ln<<<M / 2, 256>>>(lng + l * HID, lnb + l * HID);
    }

    k_head<<<(NB * NN + 7) / 8, 256>>>(hw, hb, out);
}

// round 17
// speedup vs baseline: 1.1105x; 1.0562x over previous
#include <cuda_runtime.h>
#include <cuda_bf16.h>
#include <math.h>
#include <stdint.h>

#define NB 2
#define NW 16
#define NN 1000
#define NT 16000       // NW*NN
#define FIN 16
#define ESP 16000      // spatial edges
#define DE 8
#define HID 128
#define NLAYER 3

// ---------------- scratch (device globals; no cudaMalloc allowed) ----------------
__device__ float g_x[NB * NT * HID];          // 16.4 MB
__device__ float g_qkv[NB * NT * 3 * HID];    // 49 MB   layout (row, 384): Q|K|V
__device__ float g_msg[NB * NT * HID];        // 16.4 MB
__device__ float g_y[NB * NT * HID];          // 16.4 MB
__device__ float g_film[(ESP + 1) * 2 * HID]; // 16.4 MB
__device__ float g_meanea[DE];
__device__ int   g_hist[NN];
__device__ int   g_indptr[NN + 1];
__device__ int   g_cursor[NN];
__device__ int2  g_srcpair[ESP];              // (src node, film idx) per CSR slot
// pre-split weights: 12 matrices (l*4 + {q,k,v,o}); [N=128][K=128] bf16 row-major,
// hi part in g_wA, lo part in g_wB
__device__ __nv_bfloat16 g_wA[12 * 128 * 128];
__device__ __nv_bfloat16 g_wB[12 * 128 * 128];

// ---------------- bf16 2-split helper ----------------
__device__ __forceinline__ void split2(float v, unsigned short& h, unsigned short& l) {
    __nv_bfloat16 b1 = __float2bfloat16_rn(v);
    float r = v - __bfloat162float(b1);
    __nv_bfloat16 b2 = __float2bfloat16_rn(r);
    h = __bfloat16_as_ushort(b1);
    l = __bfloat16_as_ushort(b2);
}

// ---------------- CSR build over the 1000 spatial dst nodes ----------------
__global__ void k_zero() {
    int t = blockIdx.x * blockDim.x + threadIdx.x;
    if (t < NN) g_hist[t] = 0;
}

__global__ void k_hist(const int* __restrict__ ei) {
    int j = blockIdx.x * blockDim.x + threadIdx.x;
    if (j < ESP) atomicAdd(&g_hist[ei[ESP + j]], 1);
}

__global__ void k_scan() {   // 1 block, 1024 threads
    __shared__ int sh[1024];
    int t = threadIdx.x;
    int v = (t < NN) ? g_hist[t] : 0;
    sh[t] = v;
    __syncthreads();
    for (int off = 1; off < 1024; off <<= 1) {
        int u = (t >= off) ? sh[t - off] : 0;
        __syncthreads();
        sh[t] += u;
        __syncthreads();
    }
    if (t < NN) { g_indptr[t + 1] = sh[t]; g_cursor[t] = sh[t] - v; }
    if (t == 0) g_indptr[0] = 0;
}

// fills CSR slots with flattened (src, film-idx) pairs — kills one dependent
// L2 load in the attention chain
__global__ void k_fill(const int* __restrict__ ei) {
    int j = blockIdx.x * blockDim.x + threadIdx.x;
    if (j < ESP) {
        int d = ei[ESP + j];
        int p = atomicAdd(&g_cursor[d], 1);
        g_srcpair[p] = make_int2(ei[j], j);
    }
}

// ---------------- mean of spatial edge attrs ----------------
__global__ void k_meanea(const float* __restrict__ ea) {
    __shared__ float sh[256];
    int t = threadIdx.x, c = blockIdx.x;
    float s = 0.f;
    for (int r = t; r < ESP; r += 256) s += ea[r * DE + c];
    sh[t] = s;
    __syncthreads();
    for (int off = 128; off; off >>= 1) {
        if (t < off) sh[t] += sh[t + off];
        __syncthreads();
    }
    if (t == 0) g_meanea[c] = sh[0] / (float)ESP;
}

// ---------------- weight pre-split: 12 blocks, one matrix each ----------------
__global__ void __launch_bounds__(256) k_wsplit(const float* __restrict__ qw,
                                                const float* __restrict__ kw,
                                                const float* __restrict__ vw,
                                                const float* __restrict__ ow) {
    int blk = blockIdx.x;        // l*4 + s
    int l = blk >> 2, s = blk & 3;
    const float* W = (s == 0) ? qw : (s == 1) ? kw : (s == 2) ? vw : ow;
    W += (size_t)l * HID * HID;
    __nv_bfloat16* dA = g_wA + (size_t)blk * 128 * 128;
    __nv_bfloat16* dB = g_wB + (size_t)blk * 128 * 128;
    for (int idx = threadIdx.x; idx < 128 * 128; idx += 256) {
        int n = idx >> 7, k = idx & 127;
        float w = W[k * 128 + n];
        unsigned short h, lo;
        split2(w, h, lo);
        dA[n * 128 + k] = __ushort_as_bfloat16(h);
        dB[n * 128 + k] = __ushort_as_bfloat16(lo);
    }
}

// ---------------- input projection (B*NT, 16) @ (16,128) ----------------
__global__ void __launch_bounds__(128) k_inproj(const float* __restrict__ xw,
                                                const float* __restrict__ w,
                                                const float* __restrict__ b) {
    __shared__ float a[8][FIN];
    int t = threadIdx.x;
    int r0 = blockIdx.x * 8;
    a[t / 16][t % 16] = xw[(size_t)(r0 + t / 16) * FIN + (t % 16)];
    __syncthreads();
    float wk[FIN];
#pragma unroll
    for (int k = 0; k < FIN; k++) wk[k] = w[k * HID + t];
    float bb = b[t];
#pragma unroll
    for (int rr = 0; rr < 8; rr++) {
        float s = bb;
#pragma unroll
        for (int k = 0; k < FIN; k++) s += a[rr][k] * wk[k];
        g_x[(size_t)(r0 + rr) * HID + t] = s;
    }
}

// ---------------- FiLM: (16001, 8) @ (8, 256) ----------------
__global__ void __launch_bounds__(256) k_film(const float* __restrict__ ea,
                                              const float* __restrict__ fw,
                                              const float* __restrict__ fb) {
    __shared__ float at[DE];
    int j = blockIdx.x, c = threadIdx.x;
    if (c < DE) at[c] = (j < ESP) ? ea[j * DE + c] : g_meanea[c];
    __syncthreads();
    float s = fb[c];
#pragma unroll
    for (int k = 0; k < DE; k++) s += at[k] * fw[k * 256 + c];
    g_film[(size_t)j * 256 + c] = s;
}

// ================= mma.sync bf16-split-2 GEMM =================
#define KP 136
#define TILE_B (128 * KP * 2)
#define OFF_A1 0
#define OFF_A2 (TILE_B)
#define OFF_B1 (2 * TILE_B)
#define OFF_B2 (3 * TILE_B)
#define OFF_BIAS (4 * TILE_B)
#define SMEM_MMA (OFF_BIAS + 512)

#define MMA16816(D, A0, A1_, A2_, A3_, B0, B1_)                                  \
    asm volatile(                                                                \
        "mma.sync.aligned.m16n8k16.row.col.f32.bf16.bf16.f32 "                   \
        "{%0,%1,%2,%3}, {%4,%5,%6,%7}, {%8,%9}, {%0,%1,%2,%3};"                  \
        : "+f"(D[0]), "+f"(D[1]), "+f"(D[2]), "+f"(D[3])                         \
        : "r"(A0), "r"(A1_), "r"(A2_), "r"(A3_), "r"(B0), "r"(B1_))

__global__ void __launch_bounds__(256, 1)
k_gemm_mma(int mode, int matBase,
           const float* __restrict__ bq, const float* __restrict__ bk,
           const float* __restrict__ bv, int ldc) {
    extern __shared__ char smem[];
    __nv_bfloat16* sA1 = (__nv_bfloat16*)(smem + OFF_A1);
    __nv_bfloat16* sA2 = (__nv_bfloat16*)(smem + OFF_A2);
    __nv_bfloat16* sB1 = (__nv_bfloat16*)(smem + OFF_B1);
    __nv_bfloat16* sB2 = (__nv_bfloat16*)(smem + OFF_B2);
    float* sbias = (float*)(smem + OFF_BIAS);

    int tid = threadIdx.x;
    int z = blockIdx.y;
    int r0 = blockIdx.x * 128;
    int mat = matBase + z;
    int cOff = z * HID;
    const float* __restrict__ A = (mode == 0) ? g_x : g_msg;
    float* __restrict__ C = (mode == 0) ? g_qkv : g_y;
    const float* __restrict__ bias = (z == 0) ? bq : (z == 1) ? bk : bv;

    if (tid < 128) sbias[tid] = bias[tid];

    for (int idx = tid; idx < 4096; idx += 256) {
        int row = idx >> 5, k4 = (idx & 31) << 2;
        float4 a = *(const float4*)(A + (size_t)(r0 + row) * 128 + k4);
        unsigned short h0, l0, h1, l1, h2, l2, h3, l3;
        split2(a.x, h0, l0); split2(a.y, h1, l1);
        split2(a.z, h2, l2); split2(a.w, h3, l3);
        uint2 hv = make_uint2((uint32_t)h0 | ((uint32_t)h1 << 16),
                              (uint32_t)h2 | ((uint32_t)h3 << 16));
        uint2 lv = make_uint2((uint32_t)l0 | ((uint32_t)l1 << 16),
                              (uint32_t)l2 | ((uint32_t)l3 << 16));
        *(uint2*)(sA1 + row * KP + k4) = hv;
        *(uint2*)(sA2 + row * KP + k4) = lv;
    }
    {
        const uint4* srcA = (const uint4*)(g_wA + (size_t)mat * 128 * 128);
        const uint4* srcB = (const uint4*)(g_wB + (size_t)mat * 128 * 128);
        for (int i = tid; i < 2048; i += 256) {
            int row = i >> 4, q = i & 15;
            ((uint4*)(sB1 + row * KP))[q] = srcA[i];
            ((uint4*)(sB2 + row * KP))[q] = srcB[i];
        }
    }
    __syncthreads();

    int wid = tid >> 5, lane = tid & 31;
    int warpM = wid & 3, warpN = wid >> 2;
    int g = lane >> 2, tg = lane & 3;
    int mrow0 = warpM * 32;
    int ncol0 = warpN * 64;

    float acc[2][8][4];
#pragma unroll
    for (int m = 0; m < 2; m++)
#pragma unroll
        for (int nf = 0; nf < 8; nf++)
#pragma unroll
            for (int j = 0; j < 4; j++) acc[m][nf][j] = 0.f;

#pragma unroll
    for (int pass = 0; pass < 3; pass++) {
        const __nv_bfloat16* As = (pass < 2) ? sA1 : sA2;
        const __nv_bfloat16* Bs = (pass == 1) ? sB2 : sB1;
#pragma unroll
        for (int k0 = 0; k0 < 128; k0 += 16) {
            uint32_t afr[2][4];
#pragma unroll
            for (int m = 0; m < 2; m++) {
                const __nv_bfloat16* ab = As + (mrow0 + m * 16 + g) * KP + k0 + tg * 2;
                afr[m][0] = *(const uint32_t*)(ab);
                afr[m][1] = *(const uint32_t*)(ab + 8 * KP);
                afr[m][2] = *(const uint32_t*)(ab + 8);
                afr[m][3] = *(const uint32_t*)(ab + 8 * KP + 8);
            }
#pragma unroll
            for (int nf = 0; nf < 8; nf++) {
                const __nv_bfloat16* bb = Bs + (ncol0 + nf * 8 + g) * KP + k0 + tg * 2;
                uint32_t b0r = *(const uint32_t*)(bb);
                uint32_t b1r = *(const uint32_t*)(bb + 8);
                MMA16816(acc[0][nf], afr[0][0], afr[0][1], afr[0][2], afr[0][3], b0r, b1r);
                MMA16816(acc[1][nf], afr[1][0], afr[1][1], afr[1][2], afr[1][3], b0r, b1r);
            }
        }
    }

#pragma unroll
    for (int m = 0; m < 2; m++) {
        int r = r0 + mrow0 + m * 16 + g;
#pragma unroll
        for (int nf = 0; nf < 8; nf++) {
            int c = ncol0 + nf * 8 + tg * 2;
            float2 v0 = make_float2(acc[m][nf][0] + sbias[c], acc[m][nf][1] + sbias[c + 1]);
            float2 v1 = make_float2(acc[m][nf][2] + sbias[c], acc[m][nf][3] + sbias[c + 1]);
            *(float2*)(C + (size_t)r * ldc + cOff + c) = v0;
            *(float2*)(C + (size_t)(r + 8) * ldc + cOff + c) = v1;
        }
    }
}

// ================ graph attention v4: v1 structure + flattened pairs + pipeline ===========
// warp per (batch, node); per-edge chain shortened by the precomputed (src, filmIdx)
// pair and a 2-stage software pipeline (K/V/film for edge i+1 and the pair for
// edge i+2 are in flight while edge i is computed).
__global__ void __launch_bounds__(256) k_attn4() {
    int gwarp = (blockIdx.x * blockDim.x + threadIdx.x) >> 5;
    if (gwarp >= NB * NT) return;
    int lane = threadIdx.x & 31;
    int b = gwarp / NT, n = gwarp - b * NT;
    int w = n / NN, d = n - w * NN;

    const float* qrow = g_qkv + ((size_t)(b * NT + n)) * 384;
    float4 q = *(const float4*)(qrow + lane * 4);

    float m = -INFINITY, ssum = 0.f;
    float4 acc = make_float4(0.f, 0.f, 0.f, 0.f);

    int beg = g_indptr[d];
    int nsp = g_indptr[d + 1] - beg;
    int nE = nsp + (w > 0 ? 1 : 0);

    const float* kvbase = g_qkv + (size_t)b * NT * 384 + 128;
    int woff = w * NN;

    if (nE > 0) {
        // pair(i): (src node within batch, film row idx)
        int2 p0, p1;
        {
            if (0 < nsp) { int2 pr = g_srcpair[beg]; p0 = make_int2(pr.x + woff, pr.y); }
            else p0 = make_int2(n - NN, ESP);
            if (1 < nE) {
                if (1 < nsp) { int2 pr = g_srcpair[beg + 1]; p1 = make_int2(pr.x + woff, pr.y); }
                else p1 = make_int2(n - NN, ESP);
            } else p1 = p0;
        }
        // stage-0 loads
        const float* kr0 = kvbase + (size_t)p0.x * 384;
        const float* fr0 = g_film + (size_t)p0.y * 256 + lane * 4;
        float4 k0 = *(const float4*)(kr0 + lane * 4);
        float4 v0 = *(const float4*)(kr0 + 128 + lane * 4);
        float4 ga0 = *(const float4*)(fr0);
        float4 be0 = *(const float4*)(fr0 + 128);

        for (int i = 0; i < nE; i++) {
            float4 k1 = k0, v1 = v0, ga1 = ga0, be1 = be0;
            int2 p2 = p1;
            if (i + 1 < nE) {
                const float* kr1 = kvbase + (size_t)p1.x * 384;
                const float* fr1 = g_film + (size_t)p1.y * 256 + lane * 4;
                k1 = *(const float4*)(kr1 + lane * 4);
                v1 = *(const float4*)(kr1 + 128 + lane * 4);
                ga1 = *(const float4*)(fr1);
                be1 = *(const float4*)(fr1 + 128);
                if (i + 2 < nE) {
                    if (i + 2 < nsp) {
                        int2 pr = g_srcpair[beg + i + 2];
                        p2 = make_int2(pr.x + woff, pr.y);
                    } else p2 = make_int2(n - NN, ESP);
                }
            }
            // compute edge i with stage-0 registers
            float p = q.x * (k0.x * (1.f + ga0.x) + be0.x)
                    + q.y * (k0.y * (1.f + ga0.y) + be0.y)
                    + q.z * (k0.z * (1.f + ga0.z) + be0.z)
                    + q.w * (k0.w * (1.f + ga0.w) + be0.w);
            p += __shfl_xor_sync(0xffffffffu, p, 4);
            p += __shfl_xor_sync(0xffffffffu, p, 2);
            p += __shfl_xor_sync(0xffffffffu, p, 1);
            float logit = p * 0.1767766952966369f;  // 1/sqrt(32)
            float mn = fmaxf(m, logit);
            float sc = __expf(m - mn);
            float wt = __expf(logit - mn);
            ssum = ssum * sc + wt;
            acc.x = acc.x * sc + wt * v0.x;
            acc.y = acc.y * sc + wt * v0.y;
            acc.z = acc.z * sc + wt * v0.z;
            acc.w = acc.w * sc + wt * v0.w;
            m = mn;
            // rotate pipeline
            k0 = k1; v0 = v1; ga0 = ga1; be0 = be1; p1 = p2;
        }
    }

    float inv = 1.f / (ssum + 1e-16f);
    float4 o = make_float4(acc.x * inv, acc.y * inv, acc.z * inv, acc.w * inv);
    *(float4*)(g_msg + ((size_t)(b * NT + n)) * HID + lane * 4) = o;
}

// ---------------- residual + layernorm, in-place on g_x (2 rows per block) ----------------
__global__ void __launch_bounds__(256) k_ln(const float* __restrict__ gamma,
                                            const float* __restrict__ beta) {
    int row = blockIdx.x * 2 + (threadIdx.x >> 7);
    int t = threadIdx.x & 127;
    size_t idx = (size_t)row * HID + t;
    float v = g_x[idx] + g_y[idx];
    float a = v, q = v * v;
#pragma unroll
    for (int off = 16; off; off >>= 1) {
        a += __shfl_xor_sync(0xffffffffu, a, off);
        q += __shfl_xor_sync(0xffffffffu, q, off);
    }
    __shared__ float s1[8], s2[8];
    int wid = threadIdx.x >> 5;
    if ((threadIdx.x & 31) == 0) { s1[wid] = a; s2[wid] = q; }
    __syncthreads();
    int base = (threadIdx.x >> 7) << 2;    // 0 or 4
    float ta = s1[base] + s1[base + 1] + s1[base + 2] + s1[base + 3];
    float tq = s2[base] + s2[base + 1] + s2[base + 2] + s2[base + 3];
    float mu = ta * (1.f / HID);
    float var = tq * (1.f / HID) - mu * mu;
    g_x[idx] = (v - mu) * rsqrtf(var + 1e-5f) * gamma[t] + beta[t];
}

// ---------------- head ----------------
__global__ void __launch_bounds__(256) k_head(const float* __restrict__ hw,
                                              const float* __restrict__ hb,
                                              float* __restrict__ out) {
    int gwarp = (blockIdx.x * blockDim.x + threadIdx.x) >> 5;
    if (gwarp >= NB * NN) return;
    int lane = threadIdx.x & 31;
    int b = gwarp / NN, n = gwarp - b * NN;
    const float* xr = g_x + ((size_t)(b * NT + (NW - 1) * NN + n)) * HID;
    float4 xv = *(const float4*)(xr + lane * 4);
    float4 wv = *(const float4*)(hw + lane * 4);
    float p = xv.x * wv.x + xv.y * wv.y + xv.z * wv.z + xv.w * wv.w;
#pragma unroll
    for (int off = 16; off; off >>= 1) p += __shfl_xor_sync(0xffffffffu, p, off);
    if (lane == 0) {
        float z = p + hb[0];
        out[gwarp] = fmaxf(z, 0.f) + log1pf(__expf(-fabsf(z)));
    }
}

// ---------------- launch ----------------
extern "C" void kernel_launch(void* const* d_in, const int* in_sizes, int n_in,
                              void* d_out, int out_size) {
    const float* xw  = (const float*)d_in[0];
    const int*   ei  = (const int*)d_in[1];
    const float* ea  = (const float*)d_in[2];
    const float* inw = (const float*)d_in[3];
    const float* inb = (const float*)d_in[4];
    const float* qw  = (const float*)d_in[5];
    const float* qb  = (const float*)d_in[6];
    const float* kw  = (const float*)d_in[7];
    const float* kb  = (const float*)d_in[8];
    const float* vw  = (const float*)d_in[9];
    const float* vb  = (const float*)d_in[10];
    const float* fw  = (const float*)d_in[11];
    const float* fb  = (const float*)d_in[12];
    const float* ow  = (const float*)d_in[13];
    const float* ob  = (const float*)d_in[14];
    const float* lng = (const float*)d_in[15];
    const float* lnb = (const float*)d_in[16];
    const float* hw  = (const float*)d_in[17];
    const float* hb  = (const float*)d_in[18];
    float* out = (float*)d_out;

    cudaFuncSetAttribute(k_gemm_mma, cudaFuncAttributeMaxDynamicSharedMemorySize,
                         SMEM_MMA);

    // CSR over spatial dst + mean edge attr + weight pre-split
    k_zero<<<(NN + 255) / 256, 256>>>();
    k_hist<<<(ESP + 255) / 256, 256>>>(ei);
    k_scan<<<1, 1024>>>();
    k_fill<<<(ESP + 255) / 256, 256>>>(ei);
    k_meanea<<<DE, 256>>>(ea);
    k_wsplit<<<12, 256>>>(qw, kw, vw, ow);

    // input projection
    k_inproj<<<(NB * NT) / 8, 128>>>(xw, inw, inb);

    const int M = NB * NT;  // 32000
    dim3 gQKV(M / 128, 3);
    dim3 gO(M / 128, 1);

    for (int l = 0; l < NLAYER; l++) {
        k_film<<<ESP + 1, 256>>>(ea, fw + (size_t)l * DE * 256, fb + (size_t)l * 256);
        k_gemm_mma<<<gQKV, 256, SMEM_MMA>>>(0, l * 4,
                                            qb + l * HID, kb + l * HID, vb + l * HID,
                                            384);
        k_attn4<<<(NB * NT) / 8, 256>>>();
        k_gemm_mma<<<gO, 256, SMEM_MMA>>>(1, l * 4 + 3,
                                          ob + l * HID, ob, ob, 128);
        k_ln<<<M / 2, 256>>>(lng + l * HID, lnb + l * HID);
    }

    k_head<<<(NB * NN + 7) / 8, 256>>>(hw, hb, out);
}